// round 1
// baseline (speedup 1.0000x reference)
#include <cuda_runtime.h>
#include <cuda_fp16.h>
#include <mma.h>

using namespace nvcuda;

#define NN      4096
#define IN_DIM  512
#define H       8
#define D       64
#define HD      512   // H*D

// ---------------- device scratch (static, allocation-free) ----------------
__device__ __half g_data_h[NN * IN_DIM];          // data in fp16
__device__ __half g_W_h[HD * IN_DIM];             // W in fp16
__device__ float  g_data1[NN * HD];               // data @ W^T (pre-bias)
__device__ __half g_V[H * NN * D];                // per-head V, (h, n, d)
__device__ alignas(16) float g_src[NN * H];       // (n, h)
__device__ alignas(16) float g_trg[NN * H];       // (n, h)
__device__ float  g_rowsum[H * NN];               // (h, n)
__device__ __half g_P[(size_t)H * NN * NN];       // unnormalized probs (h, i, j) — 256 MB

// ---------------- fast exp on the FMA pipe (avoid MUFU) ----------------
// exp(x) = 2^(x*log2e); |rel err| < ~4e-5 for the argument range here (x in [-0.2, ~8])
__device__ __forceinline__ float fexp(float x) {
    float y = x * 1.44269504088896f;
    float n = rintf(y);
    float f = y - n;                 // f in [-0.5, 0.5]
    float p = 1.33336e-3f;           // Taylor coeffs of 2^f
    p = fmaf(p, f, 9.61812910e-3f);
    p = fmaf(p, f, 5.55041087e-2f);
    p = fmaf(p, f, 2.40226507e-1f);
    p = fmaf(p, f, 6.93147182e-1f);
    p = fmaf(p, f, 1.0f);
    return __int_as_float(((int)n + 127) << 23) * p;
}

// ---------------- K0: fp32 -> fp16 input conversion ----------------
__global__ void k0_convert(const float* __restrict__ data, const float* __restrict__ W) {
    int i = blockIdx.x * blockDim.x + threadIdx.x;
    if (i < NN * IN_DIM) g_data_h[i] = __float2half(data[i]);
    if (i < HD * IN_DIM) g_W_h[i]    = __float2half(W[i]);
}

// ---------------- K1: data1 = data @ W^T  (wmma fp16, fp32 accum) ----------------
// grid (NN/64, HD/64), 128 threads (4 warps, each 32x32)
__global__ void k1_gemm() {
    int tm = blockIdx.x * 64;           // row (n)
    int tn = blockIdx.y * 64;           // col (hd)
    int warp = threadIdx.x >> 5;
    int wr = (warp >> 1) * 32;
    int wc = (warp & 1) * 32;

    wmma::fragment<wmma::accumulator, 16, 16, 16, float> acc[2][2];
    #pragma unroll
    for (int i = 0; i < 2; i++)
        #pragma unroll
        for (int j = 0; j < 2; j++) wmma::fill_fragment(acc[i][j], 0.0f);

    for (int k = 0; k < IN_DIM; k += 16) {
        wmma::fragment<wmma::matrix_a, 16, 16, 16, __half, wmma::row_major> a[2];
        wmma::fragment<wmma::matrix_b, 16, 16, 16, __half, wmma::col_major> b[2];
        #pragma unroll
        for (int i = 0; i < 2; i++)
            wmma::load_matrix_sync(a[i], g_data_h + (size_t)(tm + wr + i * 16) * IN_DIM + k, IN_DIM);
        #pragma unroll
        for (int j = 0; j < 2; j++)  // B[k][m] = W[m][k]: col-major view of W with ld = IN_DIM
            wmma::load_matrix_sync(b[j], g_W_h + (size_t)(tn + wc + j * 16) * IN_DIM + k, IN_DIM);
        #pragma unroll
        for (int i = 0; i < 2; i++)
            #pragma unroll
            for (int j = 0; j < 2; j++)
                wmma::mma_sync(acc[i][j], a[i], b[j], acc[i][j]);
    }
    #pragma unroll
    for (int i = 0; i < 2; i++)
        #pragma unroll
        for (int j = 0; j < 2; j++)
            wmma::store_matrix_sync(g_data1 + (size_t)(tm + wr + i * 16) * HD + tn + wc + j * 16,
                                    acc[i][j], HD, wmma::mem_row_major);
}

// ---------------- K1b: bias, V pack (fp16), src/trg projections ----------------
// grid NN, 512 threads (one per hd)
__global__ void k1b_proj(const float* __restrict__ b,
                         const float* __restrict__ sp,
                         const float* __restrict__ tp) {
    int n = blockIdx.x;
    int t = threadIdx.x;               // hd index
    int h = t >> 6, d = t & 63;
    float v = g_data1[(size_t)n * HD + t] + b[t];
    g_V[((size_t)h * NN + n) * D + d] = __float2half(v);

    __shared__ float s[HD];
    s[t] = v * sp[t];
    __syncthreads();
    #pragma unroll
    for (int off = 32; off >= 1; off >>= 1) {
        if (d < off) s[t] += s[t + off];
        __syncthreads();
    }
    if (d == 0) g_src[n * H + h] = s[t];
    __syncthreads();

    s[t] = v * tp[t];
    __syncthreads();
    #pragma unroll
    for (int off = 32; off >= 1; off >>= 1) {
        if (d < off) s[t] += s[t + off];
        __syncthreads();
    }
    if (d == 0) g_trg[n * H + h] = s[t];
}

// ---------------- K2: scores. P[h][i][j] = exp(leaky(s_i+t_j)) * [conn==0]; rowsum ----------------
// grid NN (one block per row i), 256 threads; each thread does 16 j's x 8 heads.
// conn read ONCE total (shared across heads). Masked entries produce exact 0.
__global__ void k2_scores(const float* __restrict__ conn) {
    int i = blockIdx.x;
    int tid = threadIdx.x;

    float si[H];
    #pragma unroll
    for (int h = 0; h < H; h++) si[h] = g_src[i * H + h];

    float sums[H];
    #pragma unroll
    for (int h = 0; h < H; h++) sums[h] = 0.0f;

    const float* crow = conn + (size_t)i * NN;

    #pragma unroll 4
    for (int k = 0; k < 16; k++) {
        int j = tid + (k << 8);
        float c = crow[j];
        bool edge = (c > -0.5f);       // conn is 0.0 (edge) or -1e9

        const float4* t4 = reinterpret_cast<const float4*>(g_trg + (size_t)j * H);
        float4 t0 = t4[0], t1 = t4[1];
        float tv[8] = {t0.x, t0.y, t0.z, t0.w, t1.x, t1.y, t1.z, t1.w};

        size_t base = (size_t)i * NN + j;
        #pragma unroll
        for (int h = 0; h < H; h++) {
            float p = 0.0f;
            if (edge) {
                float x = si[h] + tv[h];
                x = fmaxf(x, 0.01f * x);   // LeakyReLU(0.01)
                p = fexp(x);
            }
            sums[h] += p;
            g_P[(size_t)h * NN * NN + base] = __float2half(p);
        }
    }

    // block-reduce the 8 per-head sums
    int lane = tid & 31, wid = tid >> 5;
    __shared__ float red[H][8];
    #pragma unroll
    for (int h = 0; h < H; h++) {
        float v = sums[h];
        #pragma unroll
        for (int off = 16; off >= 1; off >>= 1) v += __shfl_down_sync(0xffffffffu, v, off);
        if (lane == 0) red[h][wid] = v;
    }
    __syncthreads();
    if (tid < H) {
        float tot = 0.0f;
        #pragma unroll
        for (int w = 0; w < 8; w++) tot += red[tid][w];
        g_rowsum[tid * NN + i] = tot;
    }
}

// ---------------- K3: out = (P[h] @ V[h]) / rowsum, per head (wmma fp16) ----------------
// grid (NN/64, H), 128 threads (4 warps). Tile 64 rows x 64 cols (=full D).
__global__ void k3_pv(float* __restrict__ out) {
    int rt = blockIdx.x * 64;
    int h  = blockIdx.y;
    int warp = threadIdx.x >> 5;
    int wr = (warp >> 1) * 32;
    int wc = (warp & 1) * 32;

    const __half* Ph = g_P + (size_t)h * NN * NN;
    const __half* Vh = g_V + (size_t)h * NN * D;

    wmma::fragment<wmma::accumulator, 16, 16, 16, float> acc[2][2];
    #pragma unroll
    for (int i = 0; i < 2; i++)
        #pragma unroll
        for (int j = 0; j < 2; j++) wmma::fill_fragment(acc[i][j], 0.0f);

    for (int k = 0; k < NN; k += 16) {
        wmma::fragment<wmma::matrix_a, 16, 16, 16, __half, wmma::row_major> a[2];
        wmma::fragment<wmma::matrix_b, 16, 16, 16, __half, wmma::row_major> b[2];
        #pragma unroll
        for (int i = 0; i < 2; i++)
            wmma::load_matrix_sync(a[i], Ph + (size_t)(rt + wr + i * 16) * NN + k, NN);
        #pragma unroll
        for (int j = 0; j < 2; j++)
            wmma::load_matrix_sync(b[j], Vh + (size_t)k * D + wc + j * 16, D);
        #pragma unroll
        for (int i = 0; i < 2; i++)
            #pragma unroll
            for (int j = 0; j < 2; j++)
                wmma::mma_sync(acc[i][j], a[i], b[j], acc[i][j]);
    }

    __shared__ float tile[64 * 64];
    #pragma unroll
    for (int i = 0; i < 2; i++)
        #pragma unroll
        for (int j = 0; j < 2; j++)
            wmma::store_matrix_sync(tile + (wr + i * 16) * 64 + wc + j * 16,
                                    acc[i][j], 64, wmma::mem_row_major);
    __syncthreads();

    for (int idx = threadIdx.x; idx < 64 * 64; idx += 128) {
        int r = idx >> 6, c = idx & 63;
        int n = rt + r;
        out[(size_t)n * HD + h * D + c] = tile[idx] / g_rowsum[h * NN + n];
    }
}

// ---------------- launcher ----------------
extern "C" void kernel_launch(void* const* d_in, const int* in_sizes, int n_in,
                              void* d_out, int out_size) {
    const float* data = (const float*)d_in[0];
    const float* conn = (const float*)d_in[1];
    const float* W    = (const float*)d_in[2];
    const float* b    = (const float*)d_in[3];
    const float* sp   = (const float*)d_in[4];
    const float* tp   = (const float*)d_in[5];
    float* out = (float*)d_out;

    k0_convert<<<(NN * IN_DIM + 255) / 256, 256>>>(data, W);
    k1_gemm<<<dim3(NN / 64, HD / 64), 128>>>();
    k1b_proj<<<NN, HD>>>(b, sp, tp);
    k2_scores<<<NN, 256>>>(conn);
    k3_pv<<<dim3(NN / 64, H), 128>>>(out);
}

// round 3
// speedup vs baseline: 1.6542x; 1.6542x over previous
#include <cuda_runtime.h>
#include <cuda_fp16.h>
#include <mma.h>

using namespace nvcuda;

#define NN      4096
#define IN_DIM  512
#define H       8
#define D       64
#define HD      512   // H*D

#define JSPLIT  8
#define JCHUNK  64
#define ROWT    64
#define JRANGE  (NN / JSPLIT)   // 512

// Ph plane: 64 rows x (64+8) halves, +8 halves tail pad; 16B-aligned rows
#define PLD       72
#define PLANE     (64 * PLD + 8)            // halves
#define PH_BYTES  (H * PLANE * 2)           // 73856
#define CONN_LD   72                        // halves per row (64 data + pad)
#define CONN_BYTES (64 * CONN_LD * 2)       // 9216
#define TRG_LD    66
#define TRG_BYTES (H * TRG_LD * 4)          // 2112
#define SMEM_BYTES (PH_BYTES + CONN_BYTES + TRG_BYTES)   // 85184

// ---------------- device scratch (static, allocation-free) ----------------
__device__ __half g_data_h[NN * IN_DIM];
__device__ __half g_W_h[HD * IN_DIM];
__device__ float  g_data1[NN * HD];
__device__ __half g_V[H * NN * D];                 // (h, n, d)
__device__ alignas(16) float g_src[NN * H];        // (n, h)
__device__ alignas(16) float g_trg[NN * H];        // (n, h)
__device__ float  g_rowsum[H * NN];                // (h, n)
__device__ float  g_opart[(size_t)JSPLIT * H * NN * D];  // 64 MB fp32 partials

// ---------------- K0: fp32 -> fp16 conversion + zero rowsum ----------------
__global__ void k0_convert(const float* __restrict__ data, const float* __restrict__ W) {
    int i = blockIdx.x * blockDim.x + threadIdx.x;
    if (i < NN * IN_DIM) g_data_h[i] = __float2half(data[i]);
    if (i < HD * IN_DIM) g_W_h[i]    = __float2half(W[i]);
    if (i < H * NN)      g_rowsum[i] = 0.0f;
}

// ---------------- K1: data1 = data @ W^T  (wmma fp16, fp32 accum) ----------------
__global__ void k1_gemm() {
    int tm = blockIdx.x * 64;
    int tn = blockIdx.y * 64;
    int warp = threadIdx.x >> 5;
    int wr = (warp >> 1) * 32;
    int wc = (warp & 1) * 32;

    wmma::fragment<wmma::accumulator, 16, 16, 16, float> acc[2][2];
    #pragma unroll
    for (int i = 0; i < 2; i++)
        #pragma unroll
        for (int j = 0; j < 2; j++) wmma::fill_fragment(acc[i][j], 0.0f);

    for (int k = 0; k < IN_DIM; k += 16) {
        wmma::fragment<wmma::matrix_a, 16, 16, 16, __half, wmma::row_major> a[2];
        wmma::fragment<wmma::matrix_b, 16, 16, 16, __half, wmma::col_major> b[2];
        #pragma unroll
        for (int i = 0; i < 2; i++)
            wmma::load_matrix_sync(a[i], g_data_h + (size_t)(tm + wr + i * 16) * IN_DIM + k, IN_DIM);
        #pragma unroll
        for (int j = 0; j < 2; j++)
            wmma::load_matrix_sync(b[j], g_W_h + (size_t)(tn + wc + j * 16) * IN_DIM + k, IN_DIM);
        #pragma unroll
        for (int i = 0; i < 2; i++)
            #pragma unroll
            for (int j = 0; j < 2; j++)
                wmma::mma_sync(acc[i][j], a[i], b[j], acc[i][j]);
    }
    #pragma unroll
    for (int i = 0; i < 2; i++)
        #pragma unroll
        for (int j = 0; j < 2; j++)
            wmma::store_matrix_sync(g_data1 + (size_t)(tm + wr + i * 16) * HD + tn + wc + j * 16,
                                    acc[i][j], HD, wmma::mem_row_major);
}

// ---------------- K1b: bias, V pack (fp16), src/trg projections ----------------
__global__ void k1b_proj(const float* __restrict__ b,
                         const float* __restrict__ sp,
                         const float* __restrict__ tp) {
    int n = blockIdx.x;
    int t = threadIdx.x;
    int h = t >> 6, d = t & 63;
    float v = g_data1[(size_t)n * HD + t] + b[t];
    g_V[((size_t)h * NN + n) * D + d] = __float2half(v);

    __shared__ float s[HD];
    s[t] = v * sp[t];
    __syncthreads();
    #pragma unroll
    for (int off = 32; off >= 1; off >>= 1) {
        if (d < off) s[t] += s[t + off];
        __syncthreads();
    }
    if (d == 0) g_src[n * H + h] = s[t];
    __syncthreads();

    s[t] = v * tp[t];
    __syncthreads();
    #pragma unroll
    for (int off = 32; off >= 1; off >>= 1) {
        if (d < off) s[t] += s[t + off];
        __syncthreads();
    }
    if (d == 0) g_trg[n * H + h] = s[t];
}

// ---------------- K2f: fused scores + PV (flash-style, P stays in smem) ----------------
// grid (NN/ROWT, JSPLIT) = (64, 8), block 512 (16 warps: 2 per head)
__global__ __launch_bounds__(512, 1) void k2f_fused(const float* __restrict__ conn) {
    extern __shared__ char sm[];
    __half* Ph   = (__half*)sm;                               // H planes of PLANE halves
    __half* connS = (__half*)(sm + PH_BYTES);                 // [64][CONN_LD], 1.0=edge
    float* trgS  = (float*)(sm + PH_BYTES + CONN_BYTES);      // [H][TRG_LD]

    const int i0    = blockIdx.x * ROWT;
    const int jbase = blockIdx.y * JRANGE;
    const int tid   = threadIdx.x;
    const int warp  = tid >> 5;

    // compute-phase identity: thread owns (i_c, h_c) for the whole block
    const int h_c = tid & 7;
    const int i_c = tid >> 3;
    // mma-phase identity
    const int h_m = warp >> 1;
    const int dh  = (warp & 1) * 32;

    const float s_i = g_src[(i0 + i_c) * H + h_c];
    float rsum = 0.0f;

    wmma::fragment<wmma::accumulator, 16, 16, 16, float> acc[4][2];
    #pragma unroll
    for (int it = 0; it < 4; it++)
        #pragma unroll
        for (int nn = 0; nn < 2; nn++) wmma::fill_fragment(acc[it][nn], 0.0f);

    const __half* Vh = g_V + (size_t)h_m * NN * D;

    for (int jc = 0; jc < JRANGE; jc += JCHUNK) {
        const int j0 = jbase + jc;

        // ---- stage conn tile (as half 0/1) + trg chunk ----
        {
            // 512 threads x 8 iters: each thread covers 4 cols (float4) of one row
            int r = tid >> 4;               // 0..31
            int c4 = (tid & 15) << 2;       // 0,4,...,60
            #pragma unroll
            for (int rr = 0; rr < 2; rr++) {
                int row = r + 32 * rr;
                const float4 cv = *(const float4*)(conn + (size_t)(i0 + row) * NN + j0 + c4);
                __half* dst = connS + row * CONN_LD + c4;
                dst[0] = __float2half(cv.x > -0.5f ? 1.0f : 0.0f);
                dst[1] = __float2half(cv.y > -0.5f ? 1.0f : 0.0f);
                dst[2] = __float2half(cv.z > -0.5f ? 1.0f : 0.0f);
                dst[3] = __float2half(cv.w > -0.5f ? 1.0f : 0.0f);
            }
            int jj = tid >> 3, hh = tid & 7;
            trgS[hh * TRG_LD + jj] = g_trg[(j0 + jj) * H + hh];
        }
        __syncthreads();

        // ---- compute P chunk: thread covers (i_c, h_c) x 64 j ----
        {
            __half* prow = Ph + h_c * PLANE + i_c * PLD;
            const __half* crow = connS + i_c * CONN_LD;
            const float* trow = trgS + h_c * TRG_LD;
            #pragma unroll 4
            for (int j = 0; j < JCHUNK; j += 2) {
                __half2 c2 = *(const __half2*)(crow + j);
                bool e0 = __low2float(c2) != 0.0f;
                bool e1 = __high2float(c2) != 0.0f;
                __half2 pv = __float2half2_rn(0.0f);
                if (__any_sync(0xffffffffu, e0 | e1)) {
                    float2 t2 = *(const float2*)(trow + j);
                    float x0 = s_i + t2.x;
                    float x1 = s_i + t2.y;
                    x0 = fmaxf(x0, 0.01f * x0);
                    x1 = fmaxf(x1, 0.01f * x1);
                    float p0 = e0 ? __expf(x0) : 0.0f;
                    float p1 = e1 ? __expf(x1) : 0.0f;
                    rsum += p0 + p1;
                    pv = __floats2half2_rn(p0, p1);
                }
                *(__half2*)(prow + j) = pv;
            }
        }
        __syncthreads();

        // ---- mma: Ph[h_m] (64x64) @ V[h_m][j0:j0+64][dh:dh+32] ----
        {
            const __half* pbase = Ph + h_m * PLANE;
            #pragma unroll
            for (int k = 0; k < 4; k++) {
                wmma::fragment<wmma::matrix_b, 16, 16, 16, __half, wmma::row_major> b[2];
                #pragma unroll
                for (int nn = 0; nn < 2; nn++)
                    wmma::load_matrix_sync(b[nn],
                        Vh + (size_t)(j0 + k * 16) * D + dh + nn * 16, D);
                #pragma unroll
                for (int it = 0; it < 4; it++) {
                    wmma::fragment<wmma::matrix_a, 16, 16, 16, __half, wmma::row_major> a;
                    wmma::load_matrix_sync(a, pbase + (it * 16) * PLD + k * 16, PLD);
                    #pragma unroll
                    for (int nn = 0; nn < 2; nn++)
                        wmma::mma_sync(acc[it][nn], a, b[nn], acc[it][nn]);
                }
            }
        }
        __syncthreads();   // protect Ph (next compute) and connS (next stage)
    }

    // ---- epilogue ----
    atomicAdd(&g_rowsum[h_c * NN + i0 + i_c], rsum);

    float* op = g_opart + (((size_t)blockIdx.y * H + h_m) * NN + i0) * D + dh;
    #pragma unroll
    for (int it = 0; it < 4; it++)
        #pragma unroll
        for (int nn = 0; nn < 2; nn++)
            wmma::store_matrix_sync(op + (size_t)(it * 16) * D + nn * 16,
                                    acc[it][nn], D, wmma::mem_row_major);
}

// ---------------- K4: out = (sum_js opart) / rowsum ----------------
__global__ void k4_final(float* __restrict__ out) {
    int idx = blockIdx.x * 256 + threadIdx.x;     // NN*HD total
    int n = idx >> 9, hd = idx & 511;
    int h = hd >> 6, d = hd & 63;
    float s = 0.0f;
    #pragma unroll
    for (int js = 0; js < JSPLIT; js++)
        s += g_opart[(((size_t)js * H + h) * NN + n) * D + d];
    out[idx] = s / g_rowsum[h * NN + n];
}

// ---------------- launcher ----------------
extern "C" void kernel_launch(void* const* d_in, const int* in_sizes, int n_in,
                              void* d_out, int out_size) {
    const float* data = (const float*)d_in[0];
    const float* conn = (const float*)d_in[1];
    const float* W    = (const float*)d_in[2];
    const float* b    = (const float*)d_in[3];
    const float* sp   = (const float*)d_in[4];
    const float* tp   = (const float*)d_in[5];
    float* out = (float*)d_out;

    cudaFuncSetAttribute(k2f_fused, cudaFuncAttributeMaxDynamicSharedMemorySize, SMEM_BYTES);

    k0_convert<<<(NN * IN_DIM + 255) / 256, 256>>>(data, W);
    k1_gemm<<<dim3(NN / 64, HD / 64), 128>>>();
    k1b_proj<<<NN, HD>>>(b, sp, tp);
    k2f_fused<<<dim3(NN / ROWT, JSPLIT), 512, SMEM_BYTES>>>(conn);
    k4_final<<<(NN * HD) / 256, 256>>>(out);
}